// round 16
// baseline (speedup 1.0000x reference)
#include <cuda_runtime.h>
#include <cuda_fp16.h>
#include <cstdint>

#define NN 50000
#define EE 800000
#define INC 128
#define HID 256
#define OUTC 15

// ---------------- scratch (static; no cudaMalloc) ----------------------------
__device__ __align__(16) int g_deg[NN];
__device__ __align__(16) int g_off[NN + 1];
__device__ __align__(16) int g_cur[NN];
__device__ __align__(16) int g_srcl[EE];
__device__ __align__(16) float g_S[(size_t)NN * HID];     // self-term partial (fp32)
__device__ __align__(16) __half g_mhi[(size_t)NN * HID];
__device__ __align__(16) __half g_mlo[(size_t)NN * HID];
__device__ __align__(16) __half g_ahi[(size_t)NN * HID];
__device__ __align__(16) __half g_alo[(size_t)NN * HID];
__device__ __align__(16) __half g_bhi[(size_t)NN * HID];
__device__ __align__(16) __half g_blo[(size_t)NN * HID];
__device__ __align__(16) __half g_wt[6 * HID * HID];

// ---------------- mma helpers (sm_80+ path) ----------------------------------
__device__ __forceinline__ void ldsm_x4(uint32_t& r0, uint32_t& r1,
                                        uint32_t& r2, uint32_t& r3, uint32_t addr) {
    asm volatile("ldmatrix.sync.aligned.m8n8.x4.shared.b16 {%0,%1,%2,%3}, [%4];"
                 : "=r"(r0), "=r"(r1), "=r"(r2), "=r"(r3) : "r"(addr));
}
__device__ __forceinline__ void mma_f16(float* d, const uint32_t* a, const uint32_t* b) {
    asm volatile("mma.sync.aligned.m16n8k16.row.col.f32.f16.f16.f32 "
                 "{%0,%1,%2,%3}, {%4,%5,%6,%7}, {%8,%9}, {%0,%1,%2,%3};"
                 : "+f"(d[0]), "+f"(d[1]), "+f"(d[2]), "+f"(d[3])
                 : "r"(a[0]), "r"(a[1]), "r"(a[2]), "r"(a[3]), "r"(b[0]), "r"(b[1]));
}

// ---------------- CSR build --------------------------------------------------
__global__ void zero_int_kernel(int* __restrict__ p, int n) {
    int i = blockIdx.x * blockDim.x + threadIdx.x;
    if (i < n) p[i] = 0;
}

__global__ void deg_kernel(const int* __restrict__ ei, int* __restrict__ deg) {
    int e = blockIdx.x * blockDim.x + threadIdx.x;
    if (e < EE) atomicAdd(&deg[ei[EE + e]], 1);
}

__global__ void scan_kernel(const int* __restrict__ deg, int* __restrict__ off,
                            int* __restrict__ cur) {
    __shared__ int part[1024];
    const int tid = threadIdx.x;
    const int CH = (NN + 1023) / 1024;
    const int base = tid * CH;
    int s = 0;
    for (int i = 0; i < CH; i++) {
        int idx = base + i;
        if (idx < NN) s += deg[idx];
    }
    part[tid] = s;
    __syncthreads();
    for (int d = 1; d < 1024; d <<= 1) {
        int v = 0;
        if (tid >= d) v = part[tid - d];
        __syncthreads();
        if (tid >= d) part[tid] += v;
        __syncthreads();
    }
    int run = (tid == 0) ? 0 : part[tid - 1];
    for (int i = 0; i < CH; i++) {
        int idx = base + i;
        if (idx < NN) {
            off[idx] = run;
            cur[idx] = run;
            run += deg[idx];
        }
    }
    if (tid == 1023) off[NN] = EE;
}

__global__ void fill_kernel(const int* __restrict__ ei, int* __restrict__ cur,
                            int* __restrict__ srcl) {
    int e = blockIdx.x * blockDim.x + threadIdx.x;
    if (e < EE) {
        int pos = atomicAdd(&cur[ei[EE + e]], 1);
        srcl[pos] = ei[e];
    }
}

// ---------------- splits -----------------------------------------------------
__global__ void split_kernel(const float* __restrict__ in,
                             __half* __restrict__ hi, __half* __restrict__ lo,
                             int n4) {
    int i = blockIdx.x * blockDim.x + threadIdx.x;
    if (i >= n4) return;
    float4 a = reinterpret_cast<const float4*>(in)[i];
    __half h0 = __float2half_rn(a.x), h1 = __float2half_rn(a.y);
    __half h2 = __float2half_rn(a.z), h3 = __float2half_rn(a.w);
    __half2 p;
    p.x = h0; p.y = h1; reinterpret_cast<__half2*>(hi)[i * 2]     = p;
    p.x = h2; p.y = h3; reinterpret_cast<__half2*>(hi)[i * 2 + 1] = p;
    p.x = __float2half_rn(a.x - __half2float(h0));
    p.y = __float2half_rn(a.y - __half2float(h1));
    reinterpret_cast<__half2*>(lo)[i * 2] = p;
    p.x = __float2half_rn(a.z - __half2float(h2));
    p.y = __float2half_rn(a.w - __half2float(h3));
    reinterpret_cast<__half2*>(lo)[i * 2 + 1] = p;
}

__global__ void wtsplit_all_kernel(const float* __restrict__ Wl1, const float* __restrict__ Wr1,
                                   const float* __restrict__ Wl2, const float* __restrict__ Wr2,
                                   const float* __restrict__ Wl3, const float* __restrict__ Wr3,
                                   __half* __restrict__ t) {
    int b = blockIdx.x;
    const float* W;
    int K, slot, lb;
    if (b < 128)        { W = Wl1; K = 128; slot = 0; lb = b; }
    else if (b < 256)   { W = Wr1; K = 128; slot = 1; lb = b - 128; }
    else if (b < 512)   { W = Wl2; K = 256; slot = 2; lb = b - 256; }
    else if (b < 768)   { W = Wr2; K = 256; slot = 3; lb = b - 512; }
    else if (b < 1024)  { W = Wl3; K = 256; slot = 4; lb = b - 768; }
    else                { W = Wr3; K = 256; slot = 5; lb = b - 1024; }
    int idx = lb * 256 + threadIdx.x;
    int n = idx & 255, k = idx >> 8;
    float v = W[(size_t)k * 256 + n];
    t[(size_t)slot * HID * HID + (size_t)n * K + k] = __float2half_rn(v);
}

// ---------------- gather helper ----------------------------------------------
__device__ __forceinline__ void add_pair8h(float* acc, uint4 vh, uint4 vl) {
    const uint32_t h[4] = {vh.x, vh.y, vh.z, vh.w};
    const uint32_t l[4] = {vl.x, vl.y, vl.z, vl.w};
    #pragma unroll
    for (int u = 0; u < 4; u++) {
        float2 fh = __half22float2(*reinterpret_cast<const __half2*>(&h[u]));
        float2 fl = __half22float2(*reinterpret_cast<const __half2*>(&l[u]));
        acc[u * 2 + 0] += fh.x + fl.x;
        acc[u * 2 + 1] += fh.y + fl.y;
    }
}

// gather one node's mean + split (MODE 0: fp32 D=128; MODE 1: fp16 D=256)
template<int MODE>
__device__ __forceinline__ void gather_node(
    int node, int lane,
    const float* __restrict__ xf,
    const __half* __restrict__ ghi, const __half* __restrict__ glo,
    const int* __restrict__ off, const int* __restrict__ srcl,
    __half* __restrict__ mhi, __half* __restrict__ mlo) {
    const int D = MODE ? HID : INC;
    const int F = D / 32;
    const int s0 = off[node], s1 = off[node + 1];
    float acc[F];
    #pragma unroll
    for (int j = 0; j < F; j++) acc[j] = 0.0f;

    if (MODE == 0) {
        int i = s0;
        for (; i + 1 < s1; i += 2) {
            float4 v0 = *reinterpret_cast<const float4*>(xf + (size_t)srcl[i] * D + lane * 4);
            float4 v1 = *reinterpret_cast<const float4*>(xf + (size_t)srcl[i + 1] * D + lane * 4);
            acc[0] += v0.x + v1.x;
            acc[1] += v0.y + v1.y;
            acc[2] += v0.z + v1.z;
            acc[3] += v0.w + v1.w;
        }
        if (i < s1) {
            float4 v0 = *reinterpret_cast<const float4*>(xf + (size_t)srcl[i] * D + lane * 4);
            acc[0] += v0.x; acc[1] += v0.y; acc[2] += v0.z; acc[3] += v0.w;
        }
    } else {
        int i = s0;
        for (; i + 1 < s1; i += 2) {
            const size_t r0 = (size_t)srcl[i] * HID + lane * 8;
            const size_t r1 = (size_t)srcl[i + 1] * HID + lane * 8;
            uint4 vh0 = *reinterpret_cast<const uint4*>(ghi + r0);
            uint4 vl0 = *reinterpret_cast<const uint4*>(glo + r0);
            uint4 vh1 = *reinterpret_cast<const uint4*>(ghi + r1);
            uint4 vl1 = *reinterpret_cast<const uint4*>(glo + r1);
            add_pair8h(acc, vh0, vl0);
            add_pair8h(acc, vh1, vl1);
        }
        if (i < s1) {
            const size_t r0 = (size_t)srcl[i] * HID + lane * 8;
            uint4 vh0 = *reinterpret_cast<const uint4*>(ghi + r0);
            uint4 vl0 = *reinterpret_cast<const uint4*>(glo + r0);
            add_pair8h(acc, vh0, vl0);
        }
    }

    const float invd = 1.0f / fmaxf((float)(s1 - s0), 1.0f);
    uint32_t ph[F / 2], pl[F / 2];
    #pragma unroll
    for (int u = 0; u < F / 2; u++) {
        float a0 = acc[2 * u] * invd, a1 = acc[2 * u + 1] * invd;
        __half2 th, tl;
        th.x = __float2half_rn(a0);
        th.y = __float2half_rn(a1);
        tl.x = __float2half_rn(a0 - __half2float(th.x));
        tl.y = __float2half_rn(a1 - __half2float(th.y));
        ph[u] = *reinterpret_cast<uint32_t*>(&th);
        pl[u] = *reinterpret_cast<uint32_t*>(&tl);
    }
    const size_t o = (size_t)node * D + lane * F;
    if (MODE == 0) {
        *reinterpret_cast<uint2*>(mhi + o) = make_uint2(ph[0], ph[1]);
        *reinterpret_cast<uint2*>(mlo + o) = make_uint2(pl[0], pl[1]);
    } else {
        *reinterpret_cast<uint4*>(mhi + o) = make_uint4(ph[0], ph[1], ph[2], ph[3]);
        *reinterpret_cast<uint4*>(mlo + o) = make_uint4(pl[0], pl[1], pl[2], pl[3]);
    }
}

// ---------------- fused gather ∥ self-GEMM (spatial partition) ----------------
// Blocks with (bid % 148) < GH are pure-gather (42 CTAs on 21 dedicated SMs);
// the other 254 CTAs run the self-pass GEMM (S = s @ Wr, fp32, no bias).
// Tile starts: group 0 -> 0..126, group 1 -> 127..253 (contiguous; stride SCTA
// covers ALL tiles — the R15 bug left starts 127..147 unvisited).
#define ROWB 144
#define ARRB (128 * ROWB)             // 18432
#define SM_BIAS_OFF (3 * ARRB)        // 55296
#define SM_TOTAL (3 * ARRB + 1024)    // 56320
#define PGRID 296
#define NTILES 782
#define GH 21                          // gather blocks per 148-group
#define GCTA (2 * GH)                  // 42 gather CTAs
#define SPG (148 - GH)                 // 127 self CTAs per group
#define SCTA (2 * SPG)                 // 254 self-GEMM CTAs

template<int MODE>   // 0: layer1 (K=128, gather fp32); 1: layers 2/3 (K=256, gather fp16)
__global__ void __launch_bounds__(256, 2)
fused_self_gather(const __half* __restrict__ shi, const __half* __restrict__ slo,
                  const __half* __restrict__ w,
                  const float* __restrict__ xf,
                  const __half* __restrict__ ghi, const __half* __restrict__ glo,
                  const int* __restrict__ off, const int* __restrict__ srcl,
                  float* __restrict__ S,
                  __half* __restrict__ mhi, __half* __restrict__ mlo) {
    constexpr int K = MODE ? HID : INC;
    extern __shared__ __align__(16) unsigned char smem[];
    const int tid  = threadIdx.x;
    const int wid  = tid >> 5;
    const int lane = tid & 31;
    const int grp  = (blockIdx.x >= 148) ? 1 : 0;
    const int m148 = blockIdx.x - grp * 148;

    if (m148 < GH) {
        // ---- gather role: warp-per-node, grid-stride over 42*8 warps ----
        const int gslot = grp * GH + m148;         // 0..41
        #pragma unroll 1
        for (int node = gslot * 8 + wid; node < NN; node += GCTA * 8)
            gather_node<MODE>(node, lane, xf, ghi, glo, off, srcl, mhi, mlo);
        return;
    }

    // ---- self-GEMM role: contiguous starts 0..SCTA-1 ----
    const int gt = grp * SPG + (m148 - GH);        // 0..253
    unsigned char* sAhi = smem;
    unsigned char* sAlo = smem + ARRB;
    unsigned char* sB   = smem + 2 * ARRB;

    const int wm = wid & 1;
    const int wn = wid >> 1;
    const uint32_t uAhi = (uint32_t)__cvta_generic_to_shared(sAhi);
    const uint32_t uAlo = (uint32_t)__cvta_generic_to_shared(sAlo);
    const uint32_t uB   = (uint32_t)__cvta_generic_to_shared(sB);

    const int a_row = (lane & 15);
    const int a_u   = (lane >> 4);
    const int b_row = (lane & 7) + ((lane & 16) >> 1);
    const int b_u   = (lane >> 3) & 1;

    #pragma unroll 1
    for (int t = gt; t < NTILES; t += SCTA) {
        const int m0 = (t >> 1) * 128;
        const int n0 = (t & 1) * 128;

        float acc[4][4][4];
        #pragma unroll
        for (int i = 0; i < 4; i++)
            #pragma unroll
            for (int j = 0; j < 4; j++)
                #pragma unroll
                for (int k = 0; k < 4; k++) acc[i][j][k] = 0.0f;

        #pragma unroll 1
        for (int kc = 0; kc < K; kc += 64) {
            __syncthreads();
            #pragma unroll
            for (int i = tid; i < 1024; i += 256) {
                int r = i >> 3, u = i & 7;
                uint4 vh = make_uint4(0, 0, 0, 0), vl = make_uint4(0, 0, 0, 0);
                int gr = m0 + r;
                if (gr < NN) {
                    size_t o = (size_t)gr * K + kc + u * 8;
                    vh = *reinterpret_cast<const uint4*>(shi + o);
                    vl = *reinterpret_cast<const uint4*>(slo + o);
                }
                int so = r * ROWB + u * 16;
                *reinterpret_cast<uint4*>(sAhi + so) = vh;
                *reinterpret_cast<uint4*>(sAlo + so) = vl;
            }
            #pragma unroll
            for (int i = tid; i < 1024; i += 256) {
                int r = i >> 3, u = i & 7;
                size_t o = (size_t)(n0 + r) * K + kc + u * 8;
                *reinterpret_cast<uint4*>(sB + r * ROWB + u * 16) =
                    *reinterpret_cast<const uint4*>(w + o);
            }
            __syncthreads();

            #pragma unroll
            for (int s = 0; s < 4; ++s) {
                uint32_t bf[2][4];
                const int bu = s * 2 + b_u;
                #pragma unroll
                for (int nfp = 0; nfp < 2; ++nfp) {
                    uint32_t o = (uint32_t)((wn * 32 + nfp * 16 + b_row) * ROWB + bu * 16);
                    ldsm_x4(bf[nfp][0], bf[nfp][1], bf[nfp][2], bf[nfp][3], uB + o);
                }
                const int au = s * 2 + a_u;
                #pragma unroll
                for (int mf = 0; mf < 4; ++mf) {
                    uint32_t ah[4], al[4];
                    uint32_t o = (uint32_t)((wm * 64 + mf * 16 + a_row) * ROWB + au * 16);
                    ldsm_x4(ah[0], ah[1], ah[2], ah[3], uAhi + o);
                    ldsm_x4(al[0], al[1], al[2], al[3], uAlo + o);
                    #pragma unroll
                    for (int nfp = 0; nfp < 2; ++nfp) {
                        #pragma unroll
                        for (int nf2 = 0; nf2 < 2; ++nf2) {
                            float* d = acc[mf][nfp * 2 + nf2];
                            mma_f16(d, ah, &bf[nfp][nf2 * 2]);
                            mma_f16(d, al, &bf[nfp][nf2 * 2]);
                        }
                    }
                }
            }
        }

        // epilogue: write fp32 partial S
        #pragma unroll
        for (int mf = 0; mf < 4; ++mf) {
            #pragma unroll
            for (int nf = 0; nf < 4; ++nf) {
                const int lc = wn * 32 + nf * 8 + (lane & 3) * 2;
                #pragma unroll
                for (int half = 0; half < 2; ++half) {
                    const int row = m0 + wm * 64 + mf * 16 + (lane >> 2) + half * 8;
                    if (row < NN) {
                        *reinterpret_cast<float2*>(S + (size_t)row * 256 + n0 + lc) =
                            make_float2(acc[mf][nf][half * 2 + 0], acc[mf][nf][half * 2 + 1]);
                    }
                }
            }
        }
    }
}

// ---------------- mean GEMM: h = relu(m @ Wl + S + bias) ----------------------
__global__ void __launch_bounds__(256, 2)
mean_gemm_kernel(const __half* __restrict__ mhi, const __half* __restrict__ mlo,
                 const __half* __restrict__ w,
                 const float* __restrict__ S, const float* __restrict__ bias,
                 __half* __restrict__ hhi, __half* __restrict__ hlo,
                 int K) {
    extern __shared__ __align__(16) unsigned char smem[];
    unsigned char* sAhi = smem;
    unsigned char* sAlo = smem + ARRB;
    unsigned char* sB   = smem + 2 * ARRB;
    float* sbias = reinterpret_cast<float*>(smem + SM_BIAS_OFF);

    const int tid  = threadIdx.x;
    const int wid  = tid >> 5;
    const int lane = tid & 31;
    const int wm   = wid & 1;
    const int wn   = wid >> 1;

    sbias[tid] = bias[tid];

    const uint32_t uAhi = (uint32_t)__cvta_generic_to_shared(sAhi);
    const uint32_t uAlo = (uint32_t)__cvta_generic_to_shared(sAlo);
    const uint32_t uB   = (uint32_t)__cvta_generic_to_shared(sB);

    const int a_row = (lane & 15);
    const int a_u   = (lane >> 4);
    const int b_row = (lane & 7) + ((lane & 16) >> 1);
    const int b_u   = (lane >> 3) & 1;

    #pragma unroll 1
    for (int t = blockIdx.x; t < NTILES; t += PGRID) {
        const int m0 = (t >> 1) * 128;
        const int n0 = (t & 1) * 128;

        float acc[4][4][4];
        #pragma unroll
        for (int i = 0; i < 4; i++)
            #pragma unroll
            for (int j = 0; j < 4; j++)
                #pragma unroll
                for (int k = 0; k < 4; k++) acc[i][j][k] = 0.0f;

        #pragma unroll 1
        for (int kc = 0; kc < K; kc += 64) {
            __syncthreads();
            #pragma unroll
            for (int i = tid; i < 1024; i += 256) {
                int r = i >> 3, u = i & 7;
                uint4 vh = make_uint4(0, 0, 0, 0), vl = make_uint4(0, 0, 0, 0);
                int gr = m0 + r;
                if (gr < NN) {
                    size_t o = (size_t)gr * K + kc + u * 8;
                    vh = *reinterpret_cast<const uint4*>(mhi + o);
                    vl = *reinterpret_cast<const uint4*>(mlo + o);
                }
                int so = r * ROWB + u * 16;
                *reinterpret_cast<uint4*>(sAhi + so) = vh;
                *reinterpret_cast<uint4*>(sAlo + so) = vl;
            }
            #pragma unroll
            for (int i = tid; i < 1024; i += 256) {
                int r = i >> 3, u = i & 7;
                size_t o = (size_t)(n0 + r) * K + kc + u * 8;
                *reinterpret_cast<uint4*>(sB + r * ROWB + u * 16) =
                    *reinterpret_cast<const uint4*>(w + o);
            }
            __syncthreads();

            #pragma unroll
            for (int s = 0; s < 4; ++s) {
                uint32_t bf[2][4];
                const int bu = s * 2 + b_u;
                #pragma unroll
                for (int nfp = 0; nfp < 2; ++nfp) {
                    uint32_t o = (uint32_t)((wn * 32 + nfp * 16 + b_row) * ROWB + bu * 16);
                    ldsm_x4(bf[nfp][0], bf[nfp][1], bf[nfp][2], bf[nfp][3], uB + o);
                }
                const int au = s * 2 + a_u;
                #pragma unroll
                for (int mf = 0; mf < 4; ++mf) {
                    uint32_t ah[4], al[4];
                    uint32_t o = (uint32_t)((wm * 64 + mf * 16 + a_row) * ROWB + au * 16);
                    ldsm_x4(ah[0], ah[1], ah[2], ah[3], uAhi + o);
                    ldsm_x4(al[0], al[1], al[2], al[3], uAlo + o);
                    #pragma unroll
                    for (int nfp = 0; nfp < 2; ++nfp) {
                        #pragma unroll
                        for (int nf2 = 0; nf2 < 2; ++nf2) {
                            float* d = acc[mf][nfp * 2 + nf2];
                            mma_f16(d, ah, &bf[nfp][nf2 * 2]);
                            mma_f16(d, al, &bf[nfp][nf2 * 2]);
                        }
                    }
                }
            }
        }

        // epilogue: + S + bias, relu, split to (hi, lo)
        #pragma unroll
        for (int mf = 0; mf < 4; ++mf) {
            #pragma unroll
            for (int nf = 0; nf < 4; ++nf) {
                const int lc = wn * 32 + nf * 8 + (lane & 3) * 2;
                const float b0 = sbias[n0 + lc], b1 = sbias[n0 + lc + 1];
                #pragma unroll
                for (int half = 0; half < 2; ++half) {
                    const int row = m0 + wm * 64 + mf * 16 + (lane >> 2) + half * 8;
                    if (row < NN) {
                        const size_t o = (size_t)row * 256 + n0 + lc;
                        const float2 sv = *reinterpret_cast<const float2*>(S + o);
                        float v0 = fmaxf(acc[mf][nf][half * 2 + 0] + sv.x + b0, 0.0f);
                        float v1 = fmaxf(acc[mf][nf][half * 2 + 1] + sv.y + b1, 0.0f);
                        __half h0 = __float2half_rn(v0);
                        __half h1 = __float2half_rn(v1);
                        __half2 ph, pl;
                        ph.x = h0; ph.y = h1;
                        pl.x = __float2half_rn(v0 - __half2float(h0));
                        pl.y = __float2half_rn(v1 - __half2float(h1));
                        *reinterpret_cast<__half2*>(hhi + o) = ph;
                        *reinterpret_cast<__half2*>(hlo + o) = pl;
                    }
                }
            }
        }
    }
}

// ---------------- output head ------------------------------------------------
__global__ void __launch_bounds__(256)
out_kernel(const __half* __restrict__ hhi, const __half* __restrict__ hlo,
           const float* __restrict__ Wo, const float* __restrict__ bo,
           float* __restrict__ out) {
    __shared__ float sW[HID * OUTC];
    __shared__ float sb[OUTC];
    const int tid = threadIdx.x;
    for (int i = tid; i < HID * OUTC; i += 256) sW[i] = Wo[i];
    if (tid < OUTC) sb[tid] = bo[tid];
    __syncthreads();

    const int warp = tid >> 5;
    const int lane = tid & 31;
    const int row = blockIdx.x * 8 + warp;
    if (row >= NN) return;

    const size_t ro = (size_t)row * HID + lane * 8;
    uint4 vh = *reinterpret_cast<const uint4*>(hhi + ro);
    uint4 vl = *reinterpret_cast<const uint4*>(hlo + ro);
    float v[8];
    {
        const uint32_t h[4] = {vh.x, vh.y, vh.z, vh.w};
        const uint32_t l[4] = {vl.x, vl.y, vl.z, vl.w};
        #pragma unroll
        for (int u = 0; u < 4; u++) {
            float2 fh = __half22float2(*reinterpret_cast<const __half2*>(&h[u]));
            float2 fl = __half22float2(*reinterpret_cast<const __half2*>(&l[u]));
            v[u * 2 + 0] = fh.x + fl.x;
            v[u * 2 + 1] = fh.y + fl.y;
        }
    }

    float a15[OUTC];
    #pragma unroll
    for (int j = 0; j < OUTC; j++) a15[j] = 0.0f;
    #pragma unroll
    for (int t = 0; t < 8; t++) {
        const int k = lane * 8 + t;
        const float* w = &sW[k * OUTC];
        #pragma unroll
        for (int j = 0; j < OUTC; j++) a15[j] = fmaf(v[t], w[j], a15[j]);
    }
    #pragma unroll
    for (int j = 0; j < OUTC; j++) {
        #pragma unroll
        for (int off = 16; off > 0; off >>= 1)
            a15[j] += __shfl_down_sync(0xffffffffu, a15[j], off);
    }
    if (lane == 0) {
        #pragma unroll
        for (int j = 0; j < OUTC; j++)
            out[(size_t)row * OUTC + j] = a15[j] + sb[j];
    }
}

// ---------------- launch ------------------------------------------------------
extern "C" void kernel_launch(void* const* d_in, const int* in_sizes, int n_in,
                              void* d_out, int out_size) {
    const float* x   = (const float*)d_in[0];
    const int*   ei  = (const int*)d_in[1];
    const float* Wl1 = (const float*)d_in[2];
    const float* bl1 = (const float*)d_in[3];
    const float* Wr1 = (const float*)d_in[4];
    const float* Wl2 = (const float*)d_in[5];
    const float* bl2 = (const float*)d_in[6];
    const float* Wr2 = (const float*)d_in[7];
    const float* Wl3 = (const float*)d_in[8];
    const float* bl3 = (const float*)d_in[9];
    const float* Wr3 = (const float*)d_in[10];
    const float* Wo  = (const float*)d_in[11];
    const float* bo  = (const float*)d_in[12];
    float* out = (float*)d_out;

    int *deg, *off, *cur, *srcl;
    float* S;
    __half *mhi, *mlo, *ahi, *alo, *bhi, *blo, *wt;
    cudaGetSymbolAddress((void**)&deg, g_deg);
    cudaGetSymbolAddress((void**)&off, g_off);
    cudaGetSymbolAddress((void**)&cur, g_cur);
    cudaGetSymbolAddress((void**)&srcl, g_srcl);
    cudaGetSymbolAddress((void**)&S,   g_S);
    cudaGetSymbolAddress((void**)&mhi, g_mhi);
    cudaGetSymbolAddress((void**)&mlo, g_mlo);
    cudaGetSymbolAddress((void**)&ahi, g_ahi);
    cudaGetSymbolAddress((void**)&alo, g_alo);
    cudaGetSymbolAddress((void**)&bhi, g_bhi);
    cudaGetSymbolAddress((void**)&blo, g_blo);
    cudaGetSymbolAddress((void**)&wt,  g_wt);

    static bool attr_set = false;
    if (!attr_set) {
        cudaFuncSetAttribute(fused_self_gather<0>,
                             cudaFuncAttributeMaxDynamicSharedMemorySize, SM_TOTAL);
        cudaFuncSetAttribute(fused_self_gather<1>,
                             cudaFuncAttributeMaxDynamicSharedMemorySize, SM_TOTAL);
        cudaFuncSetAttribute(mean_gemm_kernel,
                             cudaFuncAttributeMaxDynamicSharedMemorySize, SM_TOTAL);
        attr_set = true;
    }

    const int WSLOT = HID * HID;       // 65536
    const int GB = (NN + 7) / 8;

    // ---- CSR build ----
    zero_int_kernel<<<(NN + 255) / 256, 256>>>(deg, NN);
    deg_kernel<<<(EE + 255) / 256, 256>>>(ei, deg);
    scan_kernel<<<1, 1024>>>(deg, off, cur);
    fill_kernel<<<(EE + 255) / 256, 256>>>(ei, cur, srcl);

    // weights + x split
    wtsplit_all_kernel<<<1280, 256>>>(Wl1, Wr1, Wl2, Wr2, Wl3, Wr3, wt);
    split_kernel<<<(NN * INC / 4 + 255) / 256, 256>>>(x, ahi, alo, NN * INC / 4);

    // ---- layer 1 (K = 128): gather(x) ∥ self(ahi@Wr1) ----
    fused_self_gather<0><<<PGRID, 256, SM_TOTAL>>>(ahi, alo, wt + 1 * WSLOT,
        x, nullptr, nullptr, off, srcl, S, mhi, mlo);
    mean_gemm_kernel<<<PGRID, 256, SM_TOTAL>>>(mhi, mlo, wt + 0 * WSLOT,
        S, bl1, bhi, blo, INC);

    // ---- layer 2 (K = 256) ----
    fused_self_gather<1><<<PGRID, 256, SM_TOTAL>>>(bhi, blo, wt + 3 * WSLOT,
        nullptr, bhi, blo, off, srcl, S, mhi, mlo);
    mean_gemm_kernel<<<PGRID, 256, SM_TOTAL>>>(mhi, mlo, wt + 2 * WSLOT,
        S, bl2, ahi, alo, HID);

    // ---- layer 3 (K = 256) ----
    fused_self_gather<1><<<PGRID, 256, SM_TOTAL>>>(ahi, alo, wt + 5 * WSLOT,
        nullptr, ahi, alo, off, srcl, S, mhi, mlo);
    mean_gemm_kernel<<<PGRID, 256, SM_TOTAL>>>(mhi, mlo, wt + 4 * WSLOT,
        S, bl3, bhi, blo, HID);

    // ---- output head ----
    out_kernel<<<GB, 256>>>(bhi, blo, Wo, bo, out);
}

// round 17
// speedup vs baseline: 3.5199x; 3.5199x over previous
#include <cuda_runtime.h>
#include <cuda_fp16.h>
#include <cstdint>

#define NN 50000
#define EE 800000
#define INC 128
#define HID 256
#define OUTC 15

// ---------------- scratch (static; no cudaMalloc) ----------------------------
__device__ __align__(16) int g_deg[NN];
__device__ __align__(16) int g_off[NN + 1];
__device__ __align__(16) int g_cur[NN];
__device__ __align__(16) int g_srcl[EE];
__device__ __align__(16) __half g_m  [(size_t)NN * HID];   // mean, single fp16
__device__ __align__(16) __half g_ahi[(size_t)NN * HID];
__device__ __align__(16) __half g_alo[(size_t)NN * HID];
__device__ __align__(16) __half g_bhi[(size_t)NN * HID];
__device__ __align__(16) __half g_blo[(size_t)NN * HID];
__device__ __align__(16) __half g_wt[6 * HID * HID];       // fp16 weights (transposed)

// ---------------- mma helpers (sm_80+ path) ----------------------------------
__device__ __forceinline__ void ldsm_x4(uint32_t& r0, uint32_t& r1,
                                        uint32_t& r2, uint32_t& r3, uint32_t addr) {
    asm volatile("ldmatrix.sync.aligned.m8n8.x4.shared.b16 {%0,%1,%2,%3}, [%4];"
                 : "=r"(r0), "=r"(r1), "=r"(r2), "=r"(r3) : "r"(addr));
}
__device__ __forceinline__ void mma_f16(float* d, const uint32_t* a, const uint32_t* b) {
    asm volatile("mma.sync.aligned.m16n8k16.row.col.f32.f16.f16.f32 "
                 "{%0,%1,%2,%3}, {%4,%5,%6,%7}, {%8,%9}, {%0,%1,%2,%3};"
                 : "+f"(d[0]), "+f"(d[1]), "+f"(d[2]), "+f"(d[3])
                 : "r"(a[0]), "r"(a[1]), "r"(a[2]), "r"(a[3]), "r"(b[0]), "r"(b[1]));
}

// ---------------- CSR build --------------------------------------------------
__global__ void zero_int_kernel(int* __restrict__ p, int n) {
    int i = blockIdx.x * blockDim.x + threadIdx.x;
    if (i < n) p[i] = 0;
}

__global__ void deg_kernel(const int* __restrict__ ei, int* __restrict__ deg) {
    int e = blockIdx.x * blockDim.x + threadIdx.x;
    if (e < EE) atomicAdd(&deg[ei[EE + e]], 1);
}

__global__ void scan_kernel(const int* __restrict__ deg, int* __restrict__ off,
                            int* __restrict__ cur) {
    __shared__ int part[1024];
    const int tid = threadIdx.x;
    const int CH = (NN + 1023) / 1024;
    const int base = tid * CH;
    int s = 0;
    for (int i = 0; i < CH; i++) {
        int idx = base + i;
        if (idx < NN) s += deg[idx];
    }
    part[tid] = s;
    __syncthreads();
    for (int d = 1; d < 1024; d <<= 1) {
        int v = 0;
        if (tid >= d) v = part[tid - d];
        __syncthreads();
        if (tid >= d) part[tid] += v;
        __syncthreads();
    }
    int run = (tid == 0) ? 0 : part[tid - 1];
    for (int i = 0; i < CH; i++) {
        int idx = base + i;
        if (idx < NN) {
            off[idx] = run;
            cur[idx] = run;
            run += deg[idx];
        }
    }
    if (tid == 1023) off[NN] = EE;
}

__global__ void fill_kernel(const int* __restrict__ ei, int* __restrict__ cur,
                            int* __restrict__ srcl) {
    int e = blockIdx.x * blockDim.x + threadIdx.x;
    if (e < EE) {
        int pos = atomicAdd(&cur[ei[EE + e]], 1);
        srcl[pos] = ei[e];
    }
}

// ---------------- splits -----------------------------------------------------
// fp32 -> (hi, lo) fp16 (x features; self path keeps the split)
__global__ void split_kernel(const float* __restrict__ in,
                             __half* __restrict__ hi, __half* __restrict__ lo,
                             int n4) {
    int i = blockIdx.x * blockDim.x + threadIdx.x;
    if (i >= n4) return;
    float4 a = reinterpret_cast<const float4*>(in)[i];
    __half h0 = __float2half_rn(a.x), h1 = __float2half_rn(a.y);
    __half h2 = __float2half_rn(a.z), h3 = __float2half_rn(a.w);
    __half2 p;
    p.x = h0; p.y = h1; reinterpret_cast<__half2*>(hi)[i * 2]     = p;
    p.x = h2; p.y = h3; reinterpret_cast<__half2*>(hi)[i * 2 + 1] = p;
    p.x = __float2half_rn(a.x - __half2float(h0));
    p.y = __float2half_rn(a.y - __half2float(h1));
    reinterpret_cast<__half2*>(lo)[i * 2] = p;
    p.x = __float2half_rn(a.z - __half2float(h2));
    p.y = __float2half_rn(a.w - __half2float(h3));
    reinterpret_cast<__half2*>(lo)[i * 2 + 1] = p;
}

__global__ void wtsplit_all_kernel(const float* __restrict__ Wl1, const float* __restrict__ Wr1,
                                   const float* __restrict__ Wl2, const float* __restrict__ Wr2,
                                   const float* __restrict__ Wl3, const float* __restrict__ Wr3,
                                   __half* __restrict__ t) {
    int b = blockIdx.x;
    const float* W;
    int K, slot, lb;
    if (b < 128)        { W = Wl1; K = 128; slot = 0; lb = b; }
    else if (b < 256)   { W = Wr1; K = 128; slot = 1; lb = b - 128; }
    else if (b < 512)   { W = Wl2; K = 256; slot = 2; lb = b - 256; }
    else if (b < 768)   { W = Wr2; K = 256; slot = 3; lb = b - 512; }
    else if (b < 1024)  { W = Wl3; K = 256; slot = 4; lb = b - 768; }
    else                { W = Wr3; K = 256; slot = 5; lb = b - 1024; }
    int idx = lb * 256 + threadIdx.x;
    int n = idx & 255, k = idx >> 8;
    float v = W[(size_t)k * 256 + n];
    t[(size_t)slot * HID * HID + (size_t)n * K + k] = __float2half_rn(v);
}

// ---------------- gather mean (CSR): full-device grids, m single fp16 ---------
template<int D>
__global__ void __launch_bounds__(256)
gather_f32_kernel(const float* __restrict__ x, const int* __restrict__ off,
                  const int* __restrict__ srcl, __half* __restrict__ m) {
    const int node = blockIdx.x * 8 + (threadIdx.x >> 5);
    if (node >= NN) return;
    const int lane = threadIdx.x & 31;
    const int s0 = off[node], s1 = off[node + 1];
    const int F = D / 32;
    float acc[F];
    #pragma unroll
    for (int j = 0; j < F; j++) acc[j] = 0.0f;

    int i = s0;
    for (; i + 1 < s1; i += 2) {
        const float4* p0 = reinterpret_cast<const float4*>(x + (size_t)srcl[i] * D + lane * F);
        const float4* p1 = reinterpret_cast<const float4*>(x + (size_t)srcl[i + 1] * D + lane * F);
        #pragma unroll
        for (int u = 0; u < F / 4; u++) {
            float4 v0 = p0[u], v1 = p1[u];
            acc[u * 4 + 0] += v0.x + v1.x;
            acc[u * 4 + 1] += v0.y + v1.y;
            acc[u * 4 + 2] += v0.z + v1.z;
            acc[u * 4 + 3] += v0.w + v1.w;
        }
    }
    if (i < s1) {
        const float4* p0 = reinterpret_cast<const float4*>(x + (size_t)srcl[i] * D + lane * F);
        #pragma unroll
        for (int u = 0; u < F / 4; u++) {
            float4 v0 = p0[u];
            acc[u * 4 + 0] += v0.x;
            acc[u * 4 + 1] += v0.y;
            acc[u * 4 + 2] += v0.z;
            acc[u * 4 + 3] += v0.w;
        }
    }

    const float invd = 1.0f / fmaxf((float)(s1 - s0), 1.0f);
    uint32_t ph[F / 2];
    #pragma unroll
    for (int u = 0; u < F / 2; u++) {
        __half2 th;
        th.x = __float2half_rn(acc[2 * u] * invd);
        th.y = __float2half_rn(acc[2 * u + 1] * invd);
        ph[u] = *reinterpret_cast<uint32_t*>(&th);
    }
    const size_t o = (size_t)node * D + lane * F;
    if (F == 4) {
        *reinterpret_cast<uint2*>(m + o) = make_uint2(ph[0], ph[1]);
    } else {
        *reinterpret_cast<uint4*>(m + o) = make_uint4(ph[0], ph[1], ph[2], ph[3]);
    }
}

__device__ __forceinline__ void add_pair8h(float* acc, uint4 vh, uint4 vl) {
    const uint32_t h[4] = {vh.x, vh.y, vh.z, vh.w};
    const uint32_t l[4] = {vl.x, vl.y, vl.z, vl.w};
    #pragma unroll
    for (int u = 0; u < 4; u++) {
        float2 fh = __half22float2(*reinterpret_cast<const __half2*>(&h[u]));
        float2 fl = __half22float2(*reinterpret_cast<const __half2*>(&l[u]));
        acc[u * 2 + 0] += fh.x + fl.x;
        acc[u * 2 + 1] += fh.y + fl.y;
    }
}

__global__ void __launch_bounds__(256)
gather_f16_kernel(const __half* __restrict__ hhi, const __half* __restrict__ hlo,
                  const int* __restrict__ off, const int* __restrict__ srcl,
                  __half* __restrict__ m) {
    const int node = blockIdx.x * 8 + (threadIdx.x >> 5);
    if (node >= NN) return;
    const int lane = threadIdx.x & 31;
    const int s0 = off[node], s1 = off[node + 1];
    float acc[8];
    #pragma unroll
    for (int j = 0; j < 8; j++) acc[j] = 0.0f;

    int i = s0;
    for (; i + 1 < s1; i += 2) {
        const size_t r0 = (size_t)srcl[i] * HID + lane * 8;
        const size_t r1 = (size_t)srcl[i + 1] * HID + lane * 8;
        uint4 vh0 = *reinterpret_cast<const uint4*>(hhi + r0);
        uint4 vl0 = *reinterpret_cast<const uint4*>(hlo + r0);
        uint4 vh1 = *reinterpret_cast<const uint4*>(hhi + r1);
        uint4 vl1 = *reinterpret_cast<const uint4*>(hlo + r1);
        add_pair8h(acc, vh0, vl0);
        add_pair8h(acc, vh1, vl1);
    }
    if (i < s1) {
        const size_t r0 = (size_t)srcl[i] * HID + lane * 8;
        uint4 vh0 = *reinterpret_cast<const uint4*>(hhi + r0);
        uint4 vl0 = *reinterpret_cast<const uint4*>(hlo + r0);
        add_pair8h(acc, vh0, vl0);
    }

    const float invd = 1.0f / fmaxf((float)(s1 - s0), 1.0f);
    uint32_t ph[4];
    #pragma unroll
    for (int u = 0; u < 4; u++) {
        __half2 th;
        th.x = __float2half_rn(acc[2 * u] * invd);
        th.y = __float2half_rn(acc[2 * u + 1] * invd);
        ph[u] = *reinterpret_cast<uint32_t*>(&th);
    }
    *reinterpret_cast<uint4*>(m + (size_t)node * HID + lane * 8) =
        make_uint4(ph[0], ph[1], ph[2], ph[3]);
}

// ---------------- fp16 mma.sync SAGE GEMM (persistent, BK=64) -----------------
// pass 0 (mean): A = m single fp16, 1 mma/product.
// pass 1 (self): A = (shi, slo) split,   2 mma/product.
// B single fp16 both passes. fp32 accumulate; epilogue bias+relu -> h hi/lo.
#define ROWB 144
#define ARRB (128 * ROWB)             // 18432
#define SM_BIAS_OFF (3 * ARRB)        // 55296
#define SM_TOTAL (3 * ARRB + 1024)    // 56320
#define PGRID 296
#define NTILES 782

__global__ void __launch_bounds__(256, 2)
sage_hmma_kernel(const __half* __restrict__ m,
                 const __half* __restrict__ shi, const __half* __restrict__ slo,
                 const __half* __restrict__ wl, const __half* __restrict__ wr,
                 const float* __restrict__ bias,
                 __half* __restrict__ hhi, __half* __restrict__ hlo,
                 int K) {
    extern __shared__ __align__(16) unsigned char smem[];
    unsigned char* sAhi = smem;
    unsigned char* sAlo = smem + ARRB;
    unsigned char* sB   = smem + 2 * ARRB;
    float* sbias = reinterpret_cast<float*>(smem + SM_BIAS_OFF);

    const int tid  = threadIdx.x;
    const int wid  = tid >> 5;
    const int lane = tid & 31;
    const int wm   = wid & 1;
    const int wn   = wid >> 1;

    sbias[tid] = bias[tid];

    const uint32_t uAhi = (uint32_t)__cvta_generic_to_shared(sAhi);
    const uint32_t uAlo = (uint32_t)__cvta_generic_to_shared(sAlo);
    const uint32_t uB   = (uint32_t)__cvta_generic_to_shared(sB);

    const int a_row = (lane & 15);
    const int a_u   = (lane >> 4);
    const int b_row = (lane & 7) + ((lane & 16) >> 1);
    const int b_u   = (lane >> 3) & 1;

    #pragma unroll 1
    for (int t = blockIdx.x; t < NTILES; t += PGRID) {
        const int m0 = (t >> 1) * 128;
        const int n0 = (t & 1) * 128;

        float acc[4][4][4];
        #pragma unroll
        for (int i = 0; i < 4; i++)
            #pragma unroll
            for (int j = 0; j < 4; j++)
                #pragma unroll
                for (int k = 0; k < 4; k++) acc[i][j][k] = 0.0f;

        // ---- pass 0: mean term (single fp16 A, 1 mma) ----
        #pragma unroll 1
        for (int kc = 0; kc < K; kc += 64) {
            __syncthreads();
            #pragma unroll
            for (int i = tid; i < 1024; i += 256) {
                int r = i >> 3, u = i & 7;
                uint4 v = make_uint4(0, 0, 0, 0);
                int gr = m0 + r;
                if (gr < NN)
                    v = *reinterpret_cast<const uint4*>(m + (size_t)gr * K + kc + u * 8);
                *reinterpret_cast<uint4*>(sAhi + r * ROWB + u * 16) = v;
            }
            #pragma unroll
            for (int i = tid; i < 1024; i += 256) {
                int r = i >> 3, u = i & 7;
                size_t o = (size_t)(n0 + r) * K + kc + u * 8;
                *reinterpret_cast<uint4*>(sB + r * ROWB + u * 16) =
                    *reinterpret_cast<const uint4*>(wl + o);
            }
            __syncthreads();

            #pragma unroll
            for (int s = 0; s < 4; ++s) {
                uint32_t bf[2][4];
                const int bu = s * 2 + b_u;
                #pragma unroll
                for (int nfp = 0; nfp < 2; ++nfp) {
                    uint32_t o = (uint32_t)((wn * 32 + nfp * 16 + b_row) * ROWB + bu * 16);
                    ldsm_x4(bf[nfp][0], bf[nfp][1], bf[nfp][2], bf[nfp][3], uB + o);
                }
                const int au = s * 2 + a_u;
                #pragma unroll
                for (int mf = 0; mf < 4; ++mf) {
                    uint32_t ah[4];
                    uint32_t o = (uint32_t)((wm * 64 + mf * 16 + a_row) * ROWB + au * 16);
                    ldsm_x4(ah[0], ah[1], ah[2], ah[3], uAhi + o);
                    #pragma unroll
                    for (int nfp = 0; nfp < 2; ++nfp) {
                        #pragma unroll
                        for (int nf2 = 0; nf2 < 2; ++nf2)
                            mma_f16(acc[mf][nfp * 2 + nf2], ah, &bf[nfp][nf2 * 2]);
                    }
                }
            }
        }

        // ---- pass 1: self term (hi/lo A, 2 mma) ----
        #pragma unroll 1
        for (int kc = 0; kc < K; kc += 64) {
            __syncthreads();
            #pragma unroll
            for (int i = tid; i < 1024; i += 256) {
                int r = i >> 3, u = i & 7;
                uint4 vh = make_uint4(0, 0, 0, 0), vl = make_uint4(0, 0, 0, 0);
                int gr = m0 + r;
                if (gr < NN) {
                    size_t o = (size_t)gr * K + kc + u * 8;
                    vh = *reinterpret_cast<const uint4*>(shi + o);
                    vl = *reinterpret_cast<const uint4*>(slo + o);
                }
                int so = r * ROWB + u * 16;
                *reinterpret_cast<uint4*>(sAhi + so) = vh;
                *reinterpret_cast<uint4*>(sAlo + so) = vl;
            }
            #pragma unroll
            for (int i = tid; i < 1024; i += 256) {
                int r = i >> 3, u = i & 7;
                size_t o = (size_t)(n0 + r) * K + kc + u * 8;
                *reinterpret_cast<uint4*>(sB + r * ROWB + u * 16) =
                    *reinterpret_cast<const uint4*>(wr + o);
            }
            __syncthreads();

            #pragma unroll
            for (int s = 0; s < 4; ++s) {
                uint32_t bf[2][4];
                const int bu = s * 2 + b_u;
                #pragma unroll
                for (int nfp = 0; nfp < 2; ++nfp) {
                    uint32_t o = (uint32_t)((wn * 32 + nfp * 16 + b_row) * ROWB + bu * 16);
                    ldsm_x4(bf[nfp][0], bf[nfp][1], bf[nfp][2], bf[nfp][3], uB + o);
                }
                const int au = s * 2 + a_u;
                #pragma unroll
                for (int mf = 0; mf < 4; ++mf) {
                    uint32_t ah[4], al[4];
                    uint32_t o = (uint32_t)((wm * 64 + mf * 16 + a_row) * ROWB + au * 16);
                    ldsm_x4(ah[0], ah[1], ah[2], ah[3], uAhi + o);
                    ldsm_x4(al[0], al[1], al[2], al[3], uAlo + o);
                    #pragma unroll
                    for (int nfp = 0; nfp < 2; ++nfp) {
                        #pragma unroll
                        for (int nf2 = 0; nf2 < 2; ++nf2) {
                            float* d = acc[mf][nfp * 2 + nf2];
                            mma_f16(d, ah, &bf[nfp][nf2 * 2]);
                            mma_f16(d, al, &bf[nfp][nf2 * 2]);
                        }
                    }
                }
            }
        }

        // epilogue: bias + relu; store (hi, lo) fp16
        #pragma unroll
        for (int mf = 0; mf < 4; ++mf) {
            #pragma unroll
            for (int nf = 0; nf < 4; ++nf) {
                const int lc = wn * 32 + nf * 8 + (lane & 3) * 2;
                const float b0 = sbias[n0 + lc], b1 = sbias[n0 + lc + 1];
                #pragma unroll
                for (int half = 0; half < 2; ++half) {
                    const int row = m0 + wm * 64 + mf * 16 + (lane >> 2) + half * 8;
                    if (row < NN) {
                        float v0 = fmaxf(acc[mf][nf][half * 2 + 0] + b0, 0.0f);
                        float v1 = fmaxf(acc[mf][nf][half * 2 + 1] + b1, 0.0f);
                        size_t o = (size_t)row * 256 + n0 + lc;
                        __half h0 = __float2half_rn(v0);
                        __half h1 = __float2half_rn(v1);
                        __half2 ph, pl;
                        ph.x = h0; ph.y = h1;
                        pl.x = __float2half_rn(v0 - __half2float(h0));
                        pl.y = __float2half_rn(v1 - __half2float(h1));
                        *reinterpret_cast<__half2*>(hhi + o) = ph;
                        *reinterpret_cast<__half2*>(hlo + o) = pl;
                    }
                }
            }
        }
    }
}

// ---------------- output head ------------------------------------------------
__global__ void __launch_bounds__(256)
out_kernel(const __half* __restrict__ hhi, const __half* __restrict__ hlo,
           const float* __restrict__ Wo, const float* __restrict__ bo,
           float* __restrict__ out) {
    __shared__ float sW[HID * OUTC];
    __shared__ float sb[OUTC];
    const int tid = threadIdx.x;
    for (int i = tid; i < HID * OUTC; i += 256) sW[i] = Wo[i];
    if (tid < OUTC) sb[tid] = bo[tid];
    __syncthreads();

    const int warp = tid >> 5;
    const int lane = tid & 31;
    const int row = blockIdx.x * 8 + warp;
    if (row >= NN) return;

    const size_t ro = (size_t)row * HID + lane * 8;
    uint4 vh = *reinterpret_cast<const uint4*>(hhi + ro);
    uint4 vl = *reinterpret_cast<const uint4*>(hlo + ro);
    float v[8];
    {
        const uint32_t h[4] = {vh.x, vh.y, vh.z, vh.w};
        const uint32_t l[4] = {vl.x, vl.y, vl.z, vl.w};
        #pragma unroll
        for (int u = 0; u < 4; u++) {
            float2 fh = __half22float2(*reinterpret_cast<const __half2*>(&h[u]));
            float2 fl = __half22float2(*reinterpret_cast<const __half2*>(&l[u]));
            v[u * 2 + 0] = fh.x + fl.x;
            v[u * 2 + 1] = fh.y + fl.y;
        }
    }

    float a15[OUTC];
    #pragma unroll
    for (int j = 0; j < OUTC; j++) a15[j] = 0.0f;
    #pragma unroll
    for (int t = 0; t < 8; t++) {
        const int k = lane * 8 + t;
        const float* w = &sW[k * OUTC];
        #pragma unroll
        for (int j = 0; j < OUTC; j++) a15[j] = fmaf(v[t], w[j], a15[j]);
    }
    #pragma unroll
    for (int j = 0; j < OUTC; j++) {
        #pragma unroll
        for (int off = 16; off > 0; off >>= 1)
            a15[j] += __shfl_down_sync(0xffffffffu, a15[j], off);
    }
    if (lane == 0) {
        #pragma unroll
        for (int j = 0; j < OUTC; j++)
            out[(size_t)row * OUTC + j] = a15[j] + sb[j];
    }
}

// ---------------- launch ------------------------------------------------------
extern "C" void kernel_launch(void* const* d_in, const int* in_sizes, int n_in,
                              void* d_out, int out_size) {
    const float* x   = (const float*)d_in[0];
    const int*   ei  = (const int*)d_in[1];
    const float* Wl1 = (const float*)d_in[2];
    const float* bl1 = (const float*)d_in[3];
    const float* Wr1 = (const float*)d_in[4];
    const float* Wl2 = (const float*)d_in[5];
    const float* bl2 = (const float*)d_in[6];
    const float* Wr2 = (const float*)d_in[7];
    const float* Wl3 = (const float*)d_in[8];
    const float* bl3 = (const float*)d_in[9];
    const float* Wr3 = (const float*)d_in[10];
    const float* Wo  = (const float*)d_in[11];
    const float* bo  = (const float*)d_in[12];
    float* out = (float*)d_out;

    int *deg, *off, *cur, *srcl;
    __half *m, *ahi, *alo, *bhi, *blo, *wt;
    cudaGetSymbolAddress((void**)&deg, g_deg);
    cudaGetSymbolAddress((void**)&off, g_off);
    cudaGetSymbolAddress((void**)&cur, g_cur);
    cudaGetSymbolAddress((void**)&srcl, g_srcl);
    cudaGetSymbolAddress((void**)&m,   g_m);
    cudaGetSymbolAddress((void**)&ahi, g_ahi);
    cudaGetSymbolAddress((void**)&alo, g_alo);
    cudaGetSymbolAddress((void**)&bhi, g_bhi);
    cudaGetSymbolAddress((void**)&blo, g_blo);
    cudaGetSymbolAddress((void**)&wt,  g_wt);

    static bool attr_set = false;
    if (!attr_set) {
        cudaFuncSetAttribute(sage_hmma_kernel,
                             cudaFuncAttributeMaxDynamicSharedMemorySize, SM_TOTAL);
        attr_set = true;
    }

    const int WSLOT = HID * HID;       // 65536
    const int GB = (NN + 7) / 8;

    // ---- CSR build ----
    zero_int_kernel<<<(NN + 255) / 256, 256>>>(deg, NN);
    deg_kernel<<<(EE + 255) / 256, 256>>>(ei, deg);
    scan_kernel<<<1, 1024>>>(deg, off, cur);
    fill_kernel<<<(EE + 255) / 256, 256>>>(ei, cur, srcl);

    // weights + x split
    wtsplit_all_kernel<<<1280, 256>>>(Wl1, Wr1, Wl2, Wr2, Wl3, Wr3, wt);
    split_kernel<<<(NN * INC / 4 + 255) / 256, 256>>>(x, ahi, alo, NN * INC / 4);

    // ---- layer 1 (K = 128) ----
    gather_f32_kernel<INC><<<GB, 256>>>(x, off, srcl, m);
    sage_hmma_kernel<<<PGRID, 256, SM_TOTAL>>>(m, ahi, alo,
        wt + 0 * WSLOT, wt + 1 * WSLOT, bl1, bhi, blo, INC);

    // ---- layer 2 (K = 256) ----
    gather_f16_kernel<<<GB, 256>>>(bhi, blo, off, srcl, m);
    sage_hmma_kernel<<<PGRID, 256, SM_TOTAL>>>(m, bhi, blo,
        wt + 2 * WSLOT, wt + 3 * WSLOT, bl2, ahi, alo, HID);

    // ---- layer 3 (K = 256) ----
    gather_f16_kernel<<<GB, 256>>>(ahi, alo, off, srcl, m);
    sage_hmma_kernel<<<PGRID, 256, SM_TOTAL>>>(m, ahi, alo,
        wt + 4 * WSLOT, wt + 5 * WSLOT, bl3, bhi, blo, HID);

    // ---- output head ----
    out_kernel<<<GB, 256>>>(bhi, blo, Wo, bo, out);
}